// round 8
// baseline (speedup 1.0000x reference)
#include <cuda_runtime.h>
#include <cuda_bf16.h>
#include <cstdint>

#define BB 2
#define CIN 64
#define HIN 128
#define WIN 256
#define COUTN 64
#define KK 9
#define HO 128
#define WO 256
#define HWIN (HIN*WIN)
#define HWO (HO*WO)

// smem: S tiles 128px*128B, double-buffered hi/lo; W tiles 64cout*128B dbl hi/lo
#define SMEM_SHI(buf) ((buf)*32768)
#define SMEM_SLO(buf) ((buf)*32768 + 16384)
#define SMEM_WH(buf)  (65536 + (buf)*16384)
#define SMEM_WL(buf)  (65536 + (buf)*16384 + 8192)
#define SMEM_BYTES    98304
#define OPITCH 132

__device__ float         g_xt[(size_t)BB*HIN*WIN*CIN];   // NHWC x
__device__ __nv_bfloat16 g_wh[KK*COUTN*CIN];             // [k][cout][c]
__device__ __nv_bfloat16 g_wl[KK*COUTN*CIN];

__device__ __forceinline__ uint32_t smem_u32(const void* p) {
    uint32_t a;
    asm("{ .reg .u64 t; cvta.to.shared.u64 t, %1; cvt.u32.u64 %0, t; }" : "=r"(a) : "l"(p));
    return a;
}
#define SWZ128(o) ((o) ^ (((o) >> 3) & 0x70))

#define LDSM4(R, ADDR) \
    asm volatile("ldmatrix.sync.aligned.m8n8.x4.shared.b16 {%0,%1,%2,%3}, [%4];" \
        : "=r"((R)[0]), "=r"((R)[1]), "=r"((R)[2]), "=r"((R)[3]) : "r"(ADDR))
#define MMA16816(D, A, Bv) \
    asm volatile("mma.sync.aligned.m16n8k16.row.col.f32.bf16.bf16.f32 " \
        "{%0,%1,%2,%3}, {%4,%5,%6,%7}, {%8,%9}, {%0,%1,%2,%3};" \
        : "+f"((D)[0]), "+f"((D)[1]), "+f"((D)[2]), "+f"((D)[3]) \
        : "r"((A)[0]), "r"((A)[1]), "r"((A)[2]), "r"((A)[3]), "r"((Bv)[0]), "r"((Bv)[1]))

// ---------- fused prep ----------
__global__ __launch_bounds__(256)
void prep(const float* __restrict__ x, const float* __restrict__ w) {
    if (blockIdx.x < 2048) {
        __shared__ float t[CIN][33];
        const int bw = blockIdx.x & 7;
        const int h  = (blockIdx.x >> 3) & (HIN-1);
        const int b  = blockIdx.x >> 10;
        const int w0 = bw << 5;
        const int tw = threadIdx.x & 31, tc = threadIdx.x >> 5;
        const float* src = x + ((size_t)(b*CIN)*HIN + h)*WIN + w0 + tw;
        #pragma unroll
        for (int c = tc; c < CIN; c += 8) t[c][tw] = src[(size_t)c*HWIN];
        __syncthreads();
        const int c  = threadIdx.x & 63;
        const int wg = threadIdx.x >> 6;
        float* dst = g_xt + ((size_t)((b*HIN + h)*WIN) + w0)*CIN + c;
        #pragma unroll
        for (int i = 0; i < 8; i++) {
            int wl = (wg << 3) + i;
            dst[(size_t)wl*CIN] = t[c][wl];
        }
    } else {
        int i = (blockIdx.x - 2048) * 256 + threadIdx.x;   // [k][cout][c]
        if (i < KK*COUTN*CIN) {
            int k    = i / (COUTN*CIN);
            int rem  = i % (COUTN*CIN);
            int cout = rem >> 6;
            int c    = rem & 63;
            float v = w[cout*(CIN*KK) + c*KK + k];
            __nv_bfloat16 h = __float2bfloat16_rn(v);
            g_wh[i] = h;
            g_wl[i] = __float2bfloat16_rn(v - __bfloat162float(h));
        }
    }
}

// ---------- sampling: split issue / finish for pipelining ----------
struct Pending {
    float4 v00, v01, v10, v11;
    float4 wv;
    int p;
};

__device__ __forceinline__ Pending sample_issue(
    const float* __restrict__ xm, const float* __restrict__ offb,
    int ks, int ho, int px0, int p)
{
    Pending pd;
    pd.p = p;
    const int ki = ks / 3, kj = ks % 3;
    const float oy = __ldg(offb + (2*ks  )*HWO + p);
    const float ox = __ldg(offb + (2*ks+1)*HWO + p);
    const float py = (float)(ho - 1 + ki) + oy;
    const float px = (float)(px0 + p - 1 + kj) + ox;
    const float y0f = floorf(py), x0f = floorf(px);
    const float wy = py - y0f,   wx = px - x0f;
    const int y0 = (int)y0f, x0 = (int)x0f;
    const int y1 = y0 + 1,   x1 = x0 + 1;
    const float vy0 = (y0 >= 0 && y0 < HIN) ? 1.f : 0.f;
    const float vy1 = (y1 >= 0 && y1 < HIN) ? 1.f : 0.f;
    const float vx0 = (x0 >= 0 && x0 < WIN) ? 1.f : 0.f;
    const float vx1 = (x1 >= 0 && x1 < WIN) ? 1.f : 0.f;
    const int ya = min(max(y0, 0), HIN-1), yb = min(max(y1, 0), HIN-1);
    const int xa = min(max(x0, 0), WIN-1), xc = min(max(x1, 0), WIN-1);
    pd.wv = make_float4((1.f-wy)*(1.f-wx)*vy0*vx0, (1.f-wy)*wx*vy0*vx1,
                        wy*(1.f-wx)*vy1*vx0,       wy*wx*vy1*vx1);
    pd.v00 = __ldg((const float4*)(xm + (size_t)(ya*WIN + xa)*CIN));
    pd.v01 = __ldg((const float4*)(xm + (size_t)(ya*WIN + xc)*CIN));
    pd.v10 = __ldg((const float4*)(xm + (size_t)(yb*WIN + xa)*CIN));
    pd.v11 = __ldg((const float4*)(xm + (size_t)(yb*WIN + xc)*CIN));
    return pd;
}

__device__ __forceinline__ void sample_finish(
    char* smem, uint32_t shi, uint32_t slo, const Pending& pd, int m)
{
    const float4 wv = pd.wv;
    float4 s;
    s.x = wv.x*pd.v00.x + wv.y*pd.v01.x + wv.z*pd.v10.x + wv.w*pd.v11.x;
    s.y = wv.x*pd.v00.y + wv.y*pd.v01.y + wv.z*pd.v10.y + wv.w*pd.v11.y;
    s.z = wv.x*pd.v00.z + wv.y*pd.v01.z + wv.z*pd.v10.z + wv.w*pd.v11.z;
    s.w = wv.x*pd.v00.w + wv.y*pd.v01.w + wv.z*pd.v10.w + wv.w*pd.v11.w;
    __nv_bfloat162 h01 = __floats2bfloat162_rn(s.x, s.y);
    __nv_bfloat162 h23 = __floats2bfloat162_rn(s.z, s.w);
    __nv_bfloat162 l01 = __floats2bfloat162_rn(s.x - __bfloat162float(h01.x),
                                               s.y - __bfloat162float(h01.y));
    __nv_bfloat162 l23 = __floats2bfloat162_rn(s.z - __bfloat162float(h23.x),
                                               s.w - __bfloat162float(h23.y));
    uint32_t bo = (uint32_t)(pd.p << 7) + (m << 3);
    uint32_t so = SWZ128(bo);
    *(uint2*)(smem + shi + so) = make_uint2(*(uint32_t*)&h01, *(uint32_t*)&h23);
    *(uint2*)(smem + slo + so) = make_uint2(*(uint32_t*)&l01, *(uint32_t*)&l23);
}

// ---------- main kernel ----------
__global__ __launch_bounds__(256, 2)
void dcn_main(const float* __restrict__ off, const float* __restrict__ bias,
              float* __restrict__ out)
{
    extern __shared__ char smem[];
    const uint32_t sb = smem_u32(smem);

    const int tid  = threadIdx.x;
    const int pb   = blockIdx.x & 1;
    const int ho   = (blockIdx.x >> 1) & (HO-1);
    const int b    = blockIdx.x >> 8;
    const int px0  = pb << 7;
    const int warp = tid >> 5;
    const int lane = tid & 31;
    const int m    = lane & 15;
    const int hp   = lane >> 4;

    const float* offb = off + (size_t)b*(2*KK*HWO) + ho*WO + px0;
    const float* xb   = g_xt + (size_t)b*(HIN*WIN*CIN);
    const float* xm   = xb + (m << 2);

    float acc[8][4];
    #pragma unroll
    for (int j = 0; j < 8; j++)
        #pragma unroll
        for (int q = 0; q < 4; q++) acc[j][q] = 0.f;

    const int arow = (warp << 4) + (lane & 15);
    const uint32_t a_ch = (uint32_t)(lane >> 4) << 4;
    const int browp = ((lane >> 4) << 3) + (lane & 7);
    const uint32_t b_ch = (uint32_t)((lane >> 3) & 1) << 4;

    // ---- prologue: stage W(0), sample S(0) into buf0 ----
    {
        const uint4* srcH = (const uint4*)(g_wh);
        const uint4* srcL = (const uint4*)(g_wl);
        #pragma unroll
        for (int u = tid; u < 512; u += 256) {
            uint32_t o = u << 4, so = SWZ128(o);
            *(uint4*)(smem + SMEM_WH(0) + so) = srcH[u];
            *(uint4*)(smem + SMEM_WL(0) + so) = srcL[u];
        }
        #pragma unroll
        for (int t = 0; t < 8; t++) {
            const int p = (warp << 4) + (t << 1) + hp;
            Pending pd = sample_issue(xm, offb, 0, ho, px0, p);
            sample_finish(smem, SMEM_SHI(0), SMEM_SLO(0), pd, m);
        }
    }
    __syncthreads();

    #pragma unroll 1
    for (int k = 0; k < KK; k++) {
        const int cur = k & 1, nxt = cur ^ 1;
        const bool more = (k + 1 < KK);
        const uint32_t shi_c = SMEM_SHI(cur), slo_c = SMEM_SLO(cur);
        const uint32_t wh_c  = SMEM_WH(cur),  wl_c  = SMEM_WL(cur);

        // stage W(k+1) into next buffer
        if (more) {
            const uint4* srcH = (const uint4*)(g_wh + (k+1)*(COUTN*CIN));
            const uint4* srcL = (const uint4*)(g_wl + (k+1)*(COUTN*CIN));
            #pragma unroll
            for (int u = tid; u < 512; u += 256) {
                uint32_t o = u << 4, so = SWZ128(o);
                *(uint4*)(smem + SMEM_WH(nxt) + so) = srcH[u];
                *(uint4*)(smem + SMEM_WL(nxt) + so) = srcL[u];
            }
        }

        #pragma unroll
        for (int kc = 0; kc < 4; kc++) {
            // A(k+1): issue gather loads for 2 pixels (latency drains under MMAs)
            Pending pd0, pd1;
            if (more) {
                const int t0 = kc << 1;
                pd0 = sample_issue(xm, offb, k+1, ho, px0, (warp << 4) + (t0 << 1) + hp);
                pd1 = sample_issue(xm, offb, k+1, ho, px0, (warp << 4) + (t0 << 1) + 2 + hp);
            }

            // B(k): ldmatrix + 24 MMAs for this kc
            const uint32_t koff = (uint32_t)kc << 5;
            uint32_t ah[4], al[4];
            {
                const uint32_t addr = sb + (uint32_t)(arow << 7)
                                    + ((koff + a_ch) ^ ((uint32_t)(arow & 7) << 4));
                LDSM4(ah, addr + shi_c);
                LDSM4(al, addr + slo_c);
            }
            #pragma unroll
            for (int ntp = 0; ntp < 4; ntp++) {
                const int row = (ntp << 4) + browp;
                const uint32_t addr = sb + (uint32_t)(row << 7)
                                    + ((koff + b_ch) ^ ((uint32_t)(row & 7) << 4));
                uint32_t bh[4], bl[4];
                LDSM4(bh, addr + wh_c);
                LDSM4(bl, addr + wl_c);
                MMA16816(acc[2*ntp  ], ah, bh    );
                MMA16816(acc[2*ntp  ], ah, bl    );
                MMA16816(acc[2*ntp  ], al, bh    );
                MMA16816(acc[2*ntp+1], ah, bh + 2);
                MMA16816(acc[2*ntp+1], ah, bl + 2);
                MMA16816(acc[2*ntp+1], al, bh + 2);
            }

            // A(k+1): finish bilinear + cvt + store into next S buffer
            if (more) {
                sample_finish(smem, SMEM_SHI(nxt), SMEM_SLO(nxt), pd0, m);
                sample_finish(smem, SMEM_SHI(nxt), SMEM_SLO(nxt), pd1, m);
            }
        }
        __syncthreads();
    }

    // ---- epilogue: stage through smem, coalesced float4 writes ----
    float* s_out = (float*)smem;          // [64 cout][OPITCH]
    #pragma unroll
    for (int nt = 0; nt < 8; nt++) {
        const int c0 = (nt << 3) + ((lane & 3) << 1);
        const float b0 = __ldg(bias + c0);
        const float b1 = __ldg(bias + c0 + 1);
        const int px = (warp << 4) + (lane >> 2);
        s_out[ c0     *OPITCH + px    ] = acc[nt][0] + b0;
        s_out[(c0 + 1)*OPITCH + px    ] = acc[nt][1] + b1;
        s_out[ c0     *OPITCH + px + 8] = acc[nt][2] + b0;
        s_out[(c0 + 1)*OPITCH + px + 8] = acc[nt][3] + b1;
    }
    __syncthreads();
    {
        float* ob = out + (size_t)b*COUTN*HWO + ho*WO + px0;
        #pragma unroll
        for (int r = 0; r < 8; r++) {
            const int idx = r*256 + tid;       // 2048 float4 slots
            const int c   = idx >> 5;
            const int q   = (idx & 31) << 2;
            *(float4*)(ob + (size_t)c*HWO + q) = *(const float4*)(s_out + c*OPITCH + q);
        }
    }
}

extern "C" void kernel_launch(void* const* d_in, const int* in_sizes, int n_in,
                              void* d_out, int out_size) {
    const float* x    = (const float*)d_in[0];
    const float* off  = (const float*)d_in[1];
    const float* w    = (const float*)d_in[2];
    const float* bias = (const float*)d_in[3];
    float* out = (float*)d_out;

    cudaFuncSetAttribute(dcn_main, cudaFuncAttributeMaxDynamicSharedMemorySize, SMEM_BYTES);

    prep<<<2048 + (KK*COUTN*CIN + 255)/256, 256>>>(x, w);
    dcn_main<<<BB*HO*2, 256, SMEM_BYTES>>>(off, bias, out);
}